// round 1
// baseline (speedup 1.0000x reference)
#include <cuda_runtime.h>
#include <math_constants.h>

// ChamferLoss: B=8, N=M=4096, D=3, fp32 in, scalar fp32 out.
// dist^2 via Gram expansion: d2 = qsq + rsq - 2*dot(q,r)
// min over d2, then sqrt(eps + max(d2,0)) once per point.

#define B_DIM 8
#define N_PTS 4096
#define TPB 64          // threads per block (2 warps)
#define PTS 2           // query points per thread
#define TILE 512        // candidate points per shared tile
#define EPS 1e-8f

__global__ void zero_out_kernel(float* out) { out[0] = 0.0f; }

__global__ __launch_bounds__(TPB) void chamfer_kernel(
    const float* __restrict__ x1, const float* __restrict__ y1,
    float* __restrict__ out, float scale)
{
    __shared__ float s0[TILE];   // -2*rx
    __shared__ float s1[TILE];   // -2*ry
    __shared__ float s2[TILE];   // -2*rz
    __shared__ float srq[TILE];  // rx^2+ry^2+rz^2
    __shared__ float wsum[TPB / 32];

    const int b = blockIdx.y;
    // direction 0: queries = x1, candidates = y1 ; direction 1: swapped
    const float* Q = (blockIdx.z == 0) ? x1 : y1;
    const float* R = (blockIdx.z == 0) ? y1 : x1;
    const float* Qb = Q + (size_t)b * N_PTS * 3;
    const float* Rb = R + (size_t)b * N_PTS * 3;

    const int tid = threadIdx.x;
    // two query points per thread, coalesced-ish within block
    const int p0 = blockIdx.x * (TPB * PTS) + tid;
    const int p1 = p0 + TPB;

    const float qx0 = Qb[p0 * 3 + 0];
    const float qy0 = Qb[p0 * 3 + 1];
    const float qz0 = Qb[p0 * 3 + 2];
    const float qx1 = Qb[p1 * 3 + 0];
    const float qy1 = Qb[p1 * 3 + 1];
    const float qz1 = Qb[p1 * 3 + 2];
    const float qsq0 = fmaf(qx0, qx0, fmaf(qy0, qy0, qz0 * qz0));
    const float qsq1 = fmaf(qx1, qx1, fmaf(qy1, qy1, qz1 * qz1));

    float best0 = CUDART_INF_F;
    float best1 = CUDART_INF_F;

    for (int base = 0; base < N_PTS; base += TILE) {
        // cooperative tile load: fold -2 into candidate coords, precompute rsq
        for (int i = tid; i < TILE; i += TPB) {
            const float* r = Rb + (size_t)(base + i) * 3;
            float rx = r[0], ry = r[1], rz = r[2];
            s0[i] = -2.0f * rx;
            s1[i] = -2.0f * ry;
            s2[i] = -2.0f * rz;
            srq[i] = fmaf(rx, rx, fmaf(ry, ry, rz * rz));
        }
        __syncthreads();

        #pragma unroll 8
        for (int j = 0; j < TILE; ++j) {
            const float c0 = s0[j];
            const float c1 = s1[j];
            const float c2 = s2[j];
            const float cr = srq[j];
            // d2 = qsq + rsq - 2*dot  (3 FFMA + 1 FADD per point, LDS shared)
            float t0 = fmaf(c0, qx0, fmaf(c1, qy0, fmaf(c2, qz0, qsq0)));
            float t1 = fmaf(c0, qx1, fmaf(c1, qy1, fmaf(c2, qz1, qsq1)));
            float d20 = t0 + cr;
            float d21 = t1 + cr;
            best0 = fminf(best0, d20);
            best1 = fminf(best1, d21);
        }
        __syncthreads();
    }

    // clamp once, sqrt once per point
    float sA = sqrtf(fmaxf(best0, 0.0f) + EPS);
    float sB = sqrtf(fmaxf(best1, 0.0f) + EPS);
    float v = sA + sB;

    // warp reduce
    #pragma unroll
    for (int off = 16; off > 0; off >>= 1)
        v += __shfl_xor_sync(0xFFFFFFFFu, v, off);

    const int wid = tid >> 5;
    const int lid = tid & 31;
    if (lid == 0) wsum[wid] = v;
    __syncthreads();
    if (tid == 0) {
        float total = 0.0f;
        #pragma unroll
        for (int w = 0; w < TPB / 32; ++w) total += wsum[w];
        atomicAdd(out, total * scale);
    }
}

extern "C" void kernel_launch(void* const* d_in, const int* in_sizes, int n_in,
                              void* d_out, int out_size)
{
    const float* x1 = (const float*)d_in[0];
    const float* y1 = (const float*)d_in[1];
    float* out = (float*)d_out;

    zero_out_kernel<<<1, 1>>>(out);

    dim3 grid(N_PTS / (TPB * PTS), B_DIM, 2);  // (32, 8, 2) = 512 blocks
    const float scale = 1.0f / (float)(B_DIM * N_PTS);  // same for both directions (N==M)
    chamfer_kernel<<<grid, TPB>>>(x1, y1, out, scale);
}

// round 2
// speedup vs baseline: 1.0404x; 1.0404x over previous
#include <cuda_runtime.h>
#include <math_constants.h>

// ChamferLoss: B=8, N=M=4096, D=3, fp32 in, scalar fp32 out.
// d2' = -2*dot(q,r) + rsq  (qsq folded in AFTER the min — it's constant per query)
// Inner loop uses packed fma.rn.f32x2 (FFMA2): 2 query points per instruction.
// Candidates stored in shared pre-duplicated: (c,c) pairs -> LDS.128 gives ready
// register pairs for the packed FMA, zero per-candidate pack MOVs.

#define B_DIM 8
#define N_PTS 4096
#define TPB   64        // threads per block (2 warps)
#define PTS   4         // query points per thread (2 packed groups)
#define TILE  1024      // candidate points per shared tile
#define EPS   1e-8f

typedef unsigned long long u64;

__device__ __forceinline__ u64 ffma2(u64 a, u64 b, u64 c) {
    u64 d;
    asm("fma.rn.f32x2 %0, %1, %2, %3;" : "=l"(d) : "l"(a), "l"(b), "l"(c));
    return d;
}
__device__ __forceinline__ u64 pack2(float lo, float hi) {
    u64 d;
    asm("mov.b64 %0, {%1, %2};" : "=l"(d) : "f"(lo), "f"(hi));
    return d;
}
__device__ __forceinline__ float2 unpack2(u64 v) {
    float2 f;
    asm("mov.b64 {%0, %1}, %2;" : "=f"(f.x), "=f"(f.y) : "l"(v));
    return f;
}

__global__ void zero_out_kernel(float* out) { out[0] = 0.0f; }

__global__ __launch_bounds__(TPB) void chamfer_kernel(
    const float* __restrict__ x1, const float* __restrict__ y1,
    float* __restrict__ out, float scale)
{
    // sA[j] = { (-2rx,-2rx), (-2ry,-2ry) }   sB[j] = { (-2rz,-2rz), (rsq,rsq) }
    __shared__ ulonglong2 sA[TILE];
    __shared__ ulonglong2 sB[TILE];
    __shared__ float wsum[TPB / 32];

    const int b = blockIdx.y;
    const float* Q = (blockIdx.z == 0) ? x1 : y1;
    const float* R = (blockIdx.z == 0) ? y1 : x1;
    const float* Qb = Q + (size_t)b * N_PTS * 3;
    const float* Rb = R + (size_t)b * N_PTS * 3;

    const int tid = threadIdx.x;
    const int pbase = blockIdx.x * (TPB * PTS) + tid;

    // 4 query points: p0..p3 (stride TPB for coalescing)
    float qx[PTS], qy[PTS], qz[PTS], qsq[PTS];
    #pragma unroll
    for (int k = 0; k < PTS; ++k) {
        const int p = pbase + k * TPB;
        qx[k] = Qb[p * 3 + 0];
        qy[k] = Qb[p * 3 + 1];
        qz[k] = Qb[p * 3 + 2];
        qsq[k] = fmaf(qx[k], qx[k], fmaf(qy[k], qy[k], qz[k] * qz[k]));
    }

    // packed query register pairs: group A = (p0,p1), group B = (p2,p3)
    const u64 qxA = pack2(qx[0], qx[1]);
    const u64 qyA = pack2(qy[0], qy[1]);
    const u64 qzA = pack2(qz[0], qz[1]);
    const u64 qxB = pack2(qx[2], qx[3]);
    const u64 qyB = pack2(qy[2], qy[3]);
    const u64 qzB = pack2(qz[2], qz[3]);

    float m0 = CUDART_INF_F, m1 = CUDART_INF_F;
    float m2 = CUDART_INF_F, m3 = CUDART_INF_F;

    for (int base = 0; base < N_PTS; base += TILE) {
        // cooperative tile fill: duplicate each coefficient into a 64-bit pair
        for (int i = tid; i < TILE; i += TPB) {
            const float* r = Rb + (size_t)(base + i) * 3;
            const float rx = r[0], ry = r[1], rz = r[2];
            const float c0 = -2.0f * rx;
            const float c1 = -2.0f * ry;
            const float c2 = -2.0f * rz;
            const float cr = fmaf(rx, rx, fmaf(ry, ry, rz * rz));
            sA[i] = make_ulonglong2(pack2(c0, c0), pack2(c1, c1));
            sB[i] = make_ulonglong2(pack2(c2, c2), pack2(cr, cr));
        }
        __syncthreads();

        #pragma unroll 8
        for (int j = 0; j < TILE; ++j) {
            const ulonglong2 a = sA[j];   // (c0,c0),(c1,c1)
            const ulonglong2 bb = sB[j];  // (c2,c2),(cr,cr)
            // d2' = c0*qx + c1*qy + c2*qz + cr   (3 FFMA2 per 2 points)
            u64 tA = ffma2(bb.x, qzA, bb.y);
            tA = ffma2(a.y, qyA, tA);
            tA = ffma2(a.x, qxA, tA);
            u64 tB = ffma2(bb.x, qzB, bb.y);
            tB = ffma2(a.y, qyB, tB);
            tB = ffma2(a.x, qxB, tB);
            const float2 fA = unpack2(tA);
            const float2 fB = unpack2(tB);
            m0 = fminf(m0, fA.x);
            m1 = fminf(m1, fA.y);
            m2 = fminf(m2, fB.x);
            m3 = fminf(m3, fB.y);
        }
        __syncthreads();
    }

    // fold qsq back in, clamp, sqrt — once per point
    float v;
    {
        const float d0 = sqrtf(fmaxf(m0 + qsq[0], 0.0f) + EPS);
        const float d1 = sqrtf(fmaxf(m1 + qsq[1], 0.0f) + EPS);
        const float d2 = sqrtf(fmaxf(m2 + qsq[2], 0.0f) + EPS);
        const float d3 = sqrtf(fmaxf(m3 + qsq[3], 0.0f) + EPS);
        v = (d0 + d1) + (d2 + d3);
    }

    // warp reduce
    #pragma unroll
    for (int off = 16; off > 0; off >>= 1)
        v += __shfl_xor_sync(0xFFFFFFFFu, v, off);

    const int wid = tid >> 5;
    const int lid = tid & 31;
    if (lid == 0) wsum[wid] = v;
    __syncthreads();
    if (tid == 0) {
        float total = 0.0f;
        #pragma unroll
        for (int w = 0; w < TPB / 32; ++w) total += wsum[w];
        atomicAdd(out, total * scale);
    }
}

extern "C" void kernel_launch(void* const* d_in, const int* in_sizes, int n_in,
                              void* d_out, int out_size)
{
    const float* x1 = (const float*)d_in[0];
    const float* y1 = (const float*)d_in[1];
    float* out = (float*)d_out;

    zero_out_kernel<<<1, 1>>>(out);

    dim3 grid(N_PTS / (TPB * PTS), B_DIM, 2);  // (16, 8, 2) = 256 blocks
    const float scale = 1.0f / (float)(B_DIM * N_PTS);
    chamfer_kernel<<<grid, TPB>>>(x1, y1, out, scale);
}